// round 1
// baseline (speedup 1.0000x reference)
#include <cuda_runtime.h>
#include <math.h>
#include <stdint.h>

#define BB 256
#define NN 128
#define DD 564
#define NCLS 31
#define KP 544          // padded quadratic-dim count (512 lat + 18 smalls + 14 pad)
#define TOK (BB*NN)

// ---------------- device scratch (static: allocations are forbidden) ----------------
__device__ float  g_vp[TOK*KP];      // packed prescaled pred vectors
__device__ float  g_vt[TOK*KP];      // packed prescaled target vectors
__device__ float  g_n2p[TOK];        // ||v'||^2 over first 530 dims (pred)
__device__ float  g_n2t[TOK];        // (target)
__device__ float  g_logZ[TOK];       // logsumexp of pred class logits
__device__ int    g_cls[TOK];        // argmax class of target (first-max)
__device__ float  g_cost[TOK*NN];    // cost matrices [b][p][t]
__device__ int    g_rows[TOK];       // assignment: rows[b][t] = matched pred index
__device__ double g_acc[7];          // [ce, bmax, bmin, tr, rot, sc, la]

// ---------------- prep: pack + prescale + per-token reductions ----------------
// one warp per token (pred tokens then target tokens)
__global__ void prep_kernel(const float* __restrict__ pred, const float* __restrict__ target)
{
    if (blockIdx.x == 0 && threadIdx.x < 7) g_acc[threadIdx.x] = 0.0;

    int w    = (blockIdx.x * blockDim.x + threadIdx.x) >> 5;
    int lane = threadIdx.x & 31;
    bool isT = (w >= TOK);
    int tok  = isT ? (w - TOK) : w;

    const float* src = (isT ? target : pred) + (size_t)tok * DD;
    float*       dst = (isT ? g_vt : g_vp) + (size_t)tok * KP;

    const float s512 = 0.04419417382415922f;   // 1/sqrt(512)
    float ss = 0.f;

    // lat: dims 46..557 of src -> dims 0..511 scaled (src+46 is 8B aligned -> float2)
    const float2* s2 = (const float2*)(src + 46);
    float2*       d2 = (float2*)dst;
    #pragma unroll 4
    for (int i = lane; i < 256; i += 32) {
        float2 v = s2[i];
        float a = v.x * s512, c = v.y * s512;
        d2[i] = make_float2(a, c);
        ss = fmaf(a, a, ss);
        ss = fmaf(c, c, ss);
    }

    // smalls: bmax(31-33) bmin(34-36) tr(37-39) sc(43-45) rot(558-563), prescaled by sqrt(1/gsz)
    if (lane < 18) {
        int d = (lane < 9) ? (31 + lane) : ((lane < 12) ? (34 + lane) : (546 + lane));
        float sc = (lane < 12) ? 0.5773502691896258f   // sqrt(1/3)
                               : 0.4082482904638630f;  // sqrt(1/6)
        float vv = src[d] * sc;
        dst[512 + lane] = vv;
        ss = fmaf(vv, vv, ss);
    } else {
        dst[512 + lane] = 0.f;   // lanes 18..31 -> dims 530..543 zero pad
    }

    #pragma unroll
    for (int o = 16; o; o >>= 1) ss += __shfl_xor_sync(0xffffffffu, ss, o);
    if (lane == 0) (isT ? g_n2t : g_n2p)[tok] = ss;

    // class section
    float v = (lane < NCLS) ? src[lane] : -INFINITY;
    if (isT) {
        float bv = v; int bi = (lane < NCLS) ? lane : NCLS;
        #pragma unroll
        for (int o = 16; o; o >>= 1) {
            float ov = __shfl_xor_sync(0xffffffffu, bv, o);
            int   oi = __shfl_xor_sync(0xffffffffu, bi, o);
            if (ov > bv || (ov == bv && oi < bi)) { bv = ov; bi = oi; }
        }
        if (lane == 0) g_cls[tok] = bi;
    } else {
        float m = v;
        #pragma unroll
        for (int o = 16; o; o >>= 1) m = fmaxf(m, __shfl_xor_sync(0xffffffffu, m, o));
        float e = (lane < NCLS) ? expf(v - m) : 0.f;
        #pragma unroll
        for (int o = 16; o; o >>= 1) e += __shfl_xor_sync(0xffffffffu, e, o);
        if (lane == 0) g_logZ[tok] = m + logf(e);
    }
}

// ---------------- cost: one block per batch; 128x128x544 GEMM + epilogue ----------------
__global__ void __launch_bounds__(256, 1) cost_kernel(const float* __restrict__ pred)
{
    int b   = blockIdx.x;
    int tid = threadIdx.x;
    int tx  = tid & 15, ty = tid >> 4;

    __shared__ __align__(16) float sh[4096];     // GEMM tiles; reused as csp[128][32]
    __shared__ float s_n2p[NN], s_n2t[NN], s_logZ[NN];
    __shared__ int   s_cls[NN];

    size_t base = (size_t)b * NN;
    if (tid < NN) {
        s_n2p[tid]  = g_n2p[base + tid];
        s_n2t[tid]  = g_n2t[base + tid];
        s_logZ[tid] = g_logZ[base + tid];
        s_cls[tid]  = g_cls[base + tid];
    }

    float acc[8][8];
    #pragma unroll
    for (int i = 0; i < 8; i++)
        #pragma unroll
        for (int j = 0; j < 8; j++) acc[i][j] = 0.f;

    const float* vp = g_vp + base * KP;
    const float* vt = g_vt + base * KP;
    float* As = sh;          // [16][128] transposed tile of vp
    float* Bs = sh + 2048;   // [16][128] transposed tile of vt

    int r  = tid >> 1;
    int kc = (tid & 1) * 8;

    for (int k0 = 0; k0 < KP; k0 += 16) {
        __syncthreads();
        float4 a0 = *(const float4*)(vp + (size_t)r * KP + k0 + kc);
        float4 a1 = *(const float4*)(vp + (size_t)r * KP + k0 + kc + 4);
        float4 b0 = *(const float4*)(vt + (size_t)r * KP + k0 + kc);
        float4 b1 = *(const float4*)(vt + (size_t)r * KP + k0 + kc + 4);
        As[(kc+0)*128+r] = a0.x; As[(kc+1)*128+r] = a0.y; As[(kc+2)*128+r] = a0.z; As[(kc+3)*128+r] = a0.w;
        As[(kc+4)*128+r] = a1.x; As[(kc+5)*128+r] = a1.y; As[(kc+6)*128+r] = a1.z; As[(kc+7)*128+r] = a1.w;
        Bs[(kc+0)*128+r] = b0.x; Bs[(kc+1)*128+r] = b0.y; Bs[(kc+2)*128+r] = b0.z; Bs[(kc+3)*128+r] = b0.w;
        Bs[(kc+4)*128+r] = b1.x; Bs[(kc+5)*128+r] = b1.y; Bs[(kc+6)*128+r] = b1.z; Bs[(kc+7)*128+r] = b1.w;
        __syncthreads();

        #pragma unroll
        for (int kk = 0; kk < 16; kk++) {
            float4 av0 = *(const float4*)&As[kk*128 + ty*8];
            float4 av1 = *(const float4*)&As[kk*128 + ty*8 + 4];
            float4 bv0 = *(const float4*)&Bs[kk*128 + tx*8];
            float4 bv1 = *(const float4*)&Bs[kk*128 + tx*8 + 4];
            float av[8] = {av0.x,av0.y,av0.z,av0.w,av1.x,av1.y,av1.z,av1.w};
            float bv[8] = {bv0.x,bv0.y,bv0.z,bv0.w,bv1.x,bv1.y,bv1.z,bv1.w};
            #pragma unroll
            for (int i = 0; i < 8; i++)
                #pragma unroll
                for (int j = 0; j < 8; j++)
                    acc[i][j] = fmaf(av[i], bv[j], acc[i][j]);
        }
    }

    // reload sh as class-logit table csp[p][c] (padded to 32)
    __syncthreads();
    for (int i = tid; i < NN * NCLS; i += 256) {
        int p = i / NCLS, c = i - p * NCLS;
        sh[p*32 + c] = pred[(base + p) * DD + c];
    }
    __syncthreads();

    #pragma unroll
    for (int i = 0; i < 8; i++) {
        int p = ty*8 + i;
        float zp = s_logZ[p], np = s_n2p[p];
        float res[8];
        #pragma unroll
        for (int j = 0; j < 8; j++) {
            int t = tx*8 + j;
            float cs = zp - sh[p*32 + s_cls[t]];
            cs = fminf(cs, 18.420680743952367f);   // -log(EPS) clip
            res[j] = cs + np + s_n2t[t] - 2.0f * acc[i][j];
        }
        float4* o = (float4*)(g_cost + (base + p) * NN + tx*8);
        o[0] = make_float4(res[0], res[1], res[2], res[3]);
        o[1] = make_float4(res[4], res[5], res[6], res[7]);
    }
}

// ---------------- LSA: JV shortest-augmenting-path, one warp per batch ----------------
__global__ void lsa_kernel()
{
    extern __shared__ float C[];                 // 128x128 cost, row-major
    __shared__ float u[NN+1], v[NN+1], minv[NN+1];
    __shared__ int   p[NN+1], way[NN+1];
    __shared__ int   used[NN+1];

    int b = blockIdx.x, lane = threadIdx.x;

    const float4* src = (const float4*)(g_cost + (size_t)b * NN * NN);
    float4* dst = (float4*)C;
    for (int i = lane; i < NN*NN/4; i += 32) dst[i] = src[i];
    for (int j = lane; j <= NN; j += 32) { u[j] = 0.f; v[j] = 0.f; p[j] = 0; }
    __syncwarp();

    for (int i = 1; i <= NN; i++) {
        #pragma unroll
        for (int k = 0; k < 4; k++) { int j = lane + 1 + 32*k; minv[j] = INFINITY; used[j] = 0; }
        if (lane == 0) { p[0] = i; used[0] = 0; minv[0] = INFINITY; }
        __syncwarp();

        int j0 = 0;
        while (true) {
            if (lane == 0) used[j0] = 1;
            __syncwarp();
            int   i0  = p[j0];
            float ui0 = u[i0];

            float best = INFINITY; int bestj = 0x7fffffff;
            #pragma unroll
            for (int k = 0; k < 4; k++) {
                int j = lane + 1 + 32*k;
                if (!used[j]) {
                    float cur = C[(i0-1)*NN + (j-1)] - ui0 - v[j];
                    if (cur < minv[j]) { minv[j] = cur; way[j] = j0; }
                    float m = minv[j];
                    if (m < best) { best = m; bestj = j; }
                }
            }
            // warp argmin, first-index tie-break (matches np.argmin)
            #pragma unroll
            for (int o = 16; o; o >>= 1) {
                float ob = __shfl_xor_sync(0xffffffffu, best, o);
                int   oj = __shfl_xor_sync(0xffffffffu, bestj, o);
                if (ob < best || (ob == best && oj < bestj)) { best = ob; bestj = oj; }
            }
            float delta = best;
            __syncwarp();

            #pragma unroll
            for (int k = 0; k < 4; k++) {
                int j = lane + 1 + 32*k;
                if (used[j]) { v[j] -= delta; u[p[j]] += delta; }
                else         { minv[j] -= delta; }
            }
            if (lane == 0) u[p[0]] += delta;
            __syncwarp();

            j0 = bestj;
            if (p[j0] == 0) break;
        }
        // augment (sequential pointer chase)
        if (lane == 0) {
            int jj = j0;
            while (jj) { int j1 = way[jj]; p[jj] = p[j1]; jj = j1; }
        }
        __syncwarp();
    }

    #pragma unroll
    for (int k = 0; k < 4; k++) {
        int j = lane + 1 + 32*k;
        g_rows[b*NN + (j-1)] = p[j] - 1;
    }
}

// ---------------- matched loss: one warp per (b,t) pair ----------------
__global__ void loss_kernel(const float* __restrict__ pred)
{
    __shared__ double s_part[7];
    if (threadIdx.x < 7) s_part[threadIdx.x] = 0.0;
    __syncthreads();

    int gw   = (blockIdx.x * blockDim.x + threadIdx.x) >> 5;
    int lane = threadIdx.x & 31;
    int b = gw >> 7;
    int r = g_rows[gw];                 // gw == b*128 + t
    size_t ip = (size_t)b * NN + r;
    size_t it = (size_t)gw;

    const float4* vp = (const float4*)(g_vp + ip * KP);
    const float4* vt = (const float4*)(g_vt + it * KP);

    float sla = 0.f;                    // lat mse (already scaled by 1/512 via prescale)
    #pragma unroll
    for (int i = 0; i < 4; i++) {
        float4 a = vp[lane + 32*i];
        float4 c = vt[lane + 32*i];
        float dx = a.x - c.x, dy = a.y - c.y, dz = a.z - c.z, dw = a.w - c.w;
        sla = fmaf(dx, dx, sla); sla = fmaf(dy, dy, sla);
        sla = fmaf(dz, dz, sla); sla = fmaf(dw, dw, sla);
    }
    #pragma unroll
    for (int o = 16; o; o >>= 1) sla += __shfl_xor_sync(0xffffffffu, sla, o);

    if (lane < 18) {                    // group-mean MSEs (prescaled -> plain diff^2)
        float diff = g_vp[ip*KP + 512 + lane] - g_vt[it*KP + 512 + lane];
        // lanes: 0-2 bmax(1), 3-5 bmin(2), 6-8 tr(3), 9-11 sc(5), 12-17 rot(4)
        int s = (lane < 3) ? 1 : (lane < 6) ? 2 : (lane < 9) ? 3 : (lane < 12) ? 5 : 4;
        atomicAdd(&s_part[s], (double)(diff * diff));
    }
    if (lane == 0) {
        atomicAdd(&s_part[6], (double)sla);
        int cls = g_cls[it];
        float ce = g_logZ[ip] - pred[ip * DD + cls];
        atomicAdd(&s_part[0], (double)ce);
    }
    __syncthreads();
    if (threadIdx.x < 7) atomicAdd(&g_acc[threadIdx.x], s_part[threadIdx.x]);
}

// ---------------- finalize ----------------
__global__ void finalize_kernel(float* out, int out_size)
{
    if (threadIdx.x == 0) {
        double denom = 32768.0 + 1e-8;   // B*N + EPS
        double tot = 0.0;
        double st[7];
        for (int i = 0; i < 7; i++) { st[i] = g_acc[i]; tot += st[i]; }
        if (out_size >= 1) out[0] = (float)(tot / denom);
        for (int i = 0; i < 7; i++)
            if (out_size > i + 1) out[i + 1] = (float)(st[i] / denom);
    }
}

// ---------------- launch ----------------
extern "C" void kernel_launch(void* const* d_in, const int* in_sizes, int n_in,
                              void* d_out, int out_size)
{
    const float* pred   = (const float*)d_in[0];
    const float* target = (const float*)d_in[1];
    // d_in[2] = attention_mask: all-false, unused by reference

    cudaFuncSetAttribute(lsa_kernel, cudaFuncAttributeMaxDynamicSharedMemorySize, 65536);

    prep_kernel<<<(2*TOK)/8, 256>>>(pred, target);   // 8 warps/block
    cost_kernel<<<BB, 256>>>(pred);
    lsa_kernel<<<BB, 32, 65536>>>();
    loss_kernel<<<TOK/8, 256>>>(pred);
    finalize_kernel<<<1, 32>>>((float*)d_out, out_size);
}

// round 2
// speedup vs baseline: 2.7761x; 2.7761x over previous
#include <cuda_runtime.h>
#include <math.h>
#include <stdint.h>

#define BB 256
#define NN 128
#define DD 564
#define NCLS 31
#define KP 544          // padded quadratic-dim count (512 lat + 18 smalls + 14 pad)
#define TOK (BB*NN)

// ---------------- device scratch (static: allocations are forbidden) ----------------
__device__ float  g_vp[TOK*KP];      // packed prescaled pred vectors
__device__ float  g_vt[TOK*KP];      // packed prescaled target vectors
__device__ float  g_n2p[TOK];        // ||v'||^2 (pred)
__device__ float  g_n2t[TOK];        // (target)
__device__ float  g_logZ[TOK];       // logsumexp of pred class logits
__device__ int    g_cls[TOK];        // argmax class of target (first-max)
__device__ int    g_rows[TOK];       // assignment: rows[b][t] = matched pred index
__device__ double g_acc[7];          // [ce, bmax, bmin, tr, rot, sc, la]

// ---------------- prep: pack + prescale + per-token reductions ----------------
__global__ void prep_kernel(const float* __restrict__ pred, const float* __restrict__ target)
{
    if (blockIdx.x == 0 && threadIdx.x < 7) g_acc[threadIdx.x] = 0.0;

    int w    = (blockIdx.x * blockDim.x + threadIdx.x) >> 5;
    int lane = threadIdx.x & 31;
    bool isT = (w >= TOK);
    int tok  = isT ? (w - TOK) : w;

    const float* src = (isT ? target : pred) + (size_t)tok * DD;
    float*       dst = (isT ? g_vt : g_vp) + (size_t)tok * KP;

    const float s512 = 0.04419417382415922f;   // 1/sqrt(512)
    float ss = 0.f;

    // lat: dims 46..557 of src -> dims 0..511 scaled (src+46 is 8B aligned -> float2)
    const float2* s2 = (const float2*)(src + 46);
    float2*       d2 = (float2*)dst;
    #pragma unroll 4
    for (int i = lane; i < 256; i += 32) {
        float2 v = s2[i];
        float a = v.x * s512, c = v.y * s512;
        d2[i] = make_float2(a, c);
        ss = fmaf(a, a, ss);
        ss = fmaf(c, c, ss);
    }

    // smalls: bmax(31-33) bmin(34-36) tr(37-39) sc(43-45) rot(558-563), prescaled by sqrt(1/gsz)
    if (lane < 18) {
        int d = (lane < 9) ? (31 + lane) : ((lane < 12) ? (34 + lane) : (546 + lane));
        float sc = (lane < 12) ? 0.5773502691896258f   // sqrt(1/3)
                               : 0.4082482904638630f;  // sqrt(1/6)
        float vv = src[d] * sc;
        dst[512 + lane] = vv;
        ss = fmaf(vv, vv, ss);
    } else {
        dst[512 + lane] = 0.f;
    }

    #pragma unroll
    for (int o = 16; o; o >>= 1) ss += __shfl_xor_sync(0xffffffffu, ss, o);
    if (lane == 0) (isT ? g_n2t : g_n2p)[tok] = ss;

    // class section
    float v = (lane < NCLS) ? src[lane] : -INFINITY;
    if (isT) {
        float bv = v; int bi = (lane < NCLS) ? lane : NCLS;
        #pragma unroll
        for (int o = 16; o; o >>= 1) {
            float ov = __shfl_xor_sync(0xffffffffu, bv, o);
            int   oi = __shfl_xor_sync(0xffffffffu, bi, o);
            if (ov > bv || (ov == bv && oi < bi)) { bv = ov; bi = oi; }
        }
        if (lane == 0) g_cls[tok] = bi;
    } else {
        float m = v;
        #pragma unroll
        for (int o = 16; o; o >>= 1) m = fmaxf(m, __shfl_xor_sync(0xffffffffu, m, o));
        float e = (lane < NCLS) ? expf(v - m) : 0.f;
        #pragma unroll
        for (int o = 16; o; o >>= 1) e += __shfl_xor_sync(0xffffffffu, e, o);
        if (lane == 0) g_logZ[tok] = m + logf(e);
    }
}

// ---------------- fused cost(GEMM)+LSA: one block per batch ----------------
// dynamic smem: C[128*128] then tiles[4096]
__global__ void __launch_bounds__(256, 1) cost_lsa_kernel(const float* __restrict__ pred)
{
    extern __shared__ __align__(16) float dyn[];
    float* C     = dyn;            // 16384 floats
    float* tiles = dyn + 16384;    // 4096 floats (GEMM tiles; reused as class table)

    __shared__ float s_n2p[NN], s_n2t[NN], s_logZ[NN];
    __shared__ int   s_cls[NN];
    __shared__ float u_sh[NN+1];
    __shared__ int   p_sh[NN+1];
    __shared__ int   way_sh[NN+1];
    __shared__ int2  pc_sh[NN+1];  // {p[j], bits(u[p[j]])} frozen per row

    int b   = blockIdx.x;
    int tid = threadIdx.x;
    int tx  = tid & 15, ty = tid >> 4;
    size_t base = (size_t)b * NN;

    if (tid < NN) {
        s_n2p[tid]  = g_n2p[base + tid];
        s_n2t[tid]  = g_n2t[base + tid];
        s_logZ[tid] = g_logZ[base + tid];
        s_cls[tid]  = g_cls[base + tid];
    }

    // ---- GEMM: acc[p][t] = vp . vt over 544 dims ----
    float acc[8][8];
    #pragma unroll
    for (int i = 0; i < 8; i++)
        #pragma unroll
        for (int j = 0; j < 8; j++) acc[i][j] = 0.f;

    const float* vp = g_vp + base * KP;
    const float* vt = g_vt + base * KP;
    float* As = tiles;          // [16][128]
    float* Bs = tiles + 2048;   // [16][128]

    int r  = tid >> 1;
    int kc = (tid & 1) * 8;

    for (int k0 = 0; k0 < KP; k0 += 16) {
        __syncthreads();
        float4 a0 = *(const float4*)(vp + (size_t)r * KP + k0 + kc);
        float4 a1 = *(const float4*)(vp + (size_t)r * KP + k0 + kc + 4);
        float4 b0 = *(const float4*)(vt + (size_t)r * KP + k0 + kc);
        float4 b1 = *(const float4*)(vt + (size_t)r * KP + k0 + kc + 4);
        As[(kc+0)*128+r] = a0.x; As[(kc+1)*128+r] = a0.y; As[(kc+2)*128+r] = a0.z; As[(kc+3)*128+r] = a0.w;
        As[(kc+4)*128+r] = a1.x; As[(kc+5)*128+r] = a1.y; As[(kc+6)*128+r] = a1.z; As[(kc+7)*128+r] = a1.w;
        Bs[(kc+0)*128+r] = b0.x; Bs[(kc+1)*128+r] = b0.y; Bs[(kc+2)*128+r] = b0.z; Bs[(kc+3)*128+r] = b0.w;
        Bs[(kc+4)*128+r] = b1.x; Bs[(kc+5)*128+r] = b1.y; Bs[(kc+6)*128+r] = b1.z; Bs[(kc+7)*128+r] = b1.w;
        __syncthreads();

        #pragma unroll
        for (int kk = 0; kk < 16; kk++) {
            float4 av0 = *(const float4*)&As[kk*128 + ty*8];
            float4 av1 = *(const float4*)&As[kk*128 + ty*8 + 4];
            float4 bv0 = *(const float4*)&Bs[kk*128 + tx*8];
            float4 bv1 = *(const float4*)&Bs[kk*128 + tx*8 + 4];
            float av[8] = {av0.x,av0.y,av0.z,av0.w,av1.x,av1.y,av1.z,av1.w};
            float bv[8] = {bv0.x,bv0.y,bv0.z,bv0.w,bv1.x,bv1.y,bv1.z,bv1.w};
            #pragma unroll
            for (int i = 0; i < 8; i++)
                #pragma unroll
                for (int j = 0; j < 8; j++)
                    acc[i][j] = fmaf(av[i], bv[j], acc[i][j]);
        }
    }

    // class-logit table into tiles
    __syncthreads();
    for (int i = tid; i < NN * NCLS; i += 256) {
        int p = i / NCLS, c = i - p * NCLS;
        tiles[p*32 + c] = pred[(base + p) * DD + c];
    }
    __syncthreads();

    // epilogue: write cost into smem C
    #pragma unroll
    for (int i = 0; i < 8; i++) {
        int p = ty*8 + i;
        float zp = s_logZ[p], np = s_n2p[p];
        float res[8];
        #pragma unroll
        for (int j = 0; j < 8; j++) {
            int t = tx*8 + j;
            float cs = zp - tiles[p*32 + s_cls[t]];
            cs = fminf(cs, 18.420680743952367f);   // -log(EPS) clip
            res[j] = cs + np + s_n2t[t] - 2.0f * acc[i][j];
        }
        float4* o = (float4*)(C + p * NN + tx*8);
        o[0] = make_float4(res[0], res[1], res[2], res[3]);
        o[1] = make_float4(res[4], res[5], res[6], res[7]);
    }
    __syncthreads();

    // ---- LSA (JV, deferred dual updates), warp 0 only ----
    if (tid >= 32) return;
    int lane = tid;

    float vreg[4] = {0.f, 0.f, 0.f, 0.f};
    for (int j = lane; j <= NN; j += 32) { u_sh[j] = 0.f; p_sh[j] = 0; }
    __syncwarp();

    for (int i = 1; i <= NN; i++) {
        float minv[4] = {INFINITY, INFINITY, INFINITY, INFINITY};
        unsigned used = 0;
        if (lane == 0) p_sh[0] = i;
        __syncwarp();
        // freeze {p, u[p]} for this row's search
        #pragma unroll
        for (int k = 0; k < 5; k++) {
            int j = lane + 32*k;
            if (j <= NN) {
                int pj = p_sh[j];
                pc_sh[j] = make_int2(pj, __float_as_int(pj ? u_sh[pj] : 0.f));
            }
        }
        __syncwarp();

        int j0 = 0; float minVal = 0.f;
        int sink;
        while (true) {
            int2 pu = pc_sh[j0];
            int i0 = pu.x;
            if (i0 == 0) { sink = j0; break; }
            if (j0 > 0 && ((j0-1) & 31) == lane) used |= 1u << ((j0-1) >> 5);
            float r0 = minVal - __int_as_float(pu.y);
            const float* rowC = C + (i0-1)*NN;
            float c0 = rowC[lane], c1 = rowC[lane+32], c2 = rowC[lane+64], c3 = rowC[lane+96];

            float bestv = INFINITY; int bestj = 0x7fffffff;
            float cs[4] = {c0, c1, c2, c3};
            #pragma unroll
            for (int k = 0; k < 4; k++) {
                bool us = (used >> k) & 1;
                float cur = r0 + cs[k] - vreg[k];
                if (!us && cur < minv[k]) { minv[k] = cur; way_sh[lane + 32*k + 1] = j0; }
                float cand = us ? INFINITY : minv[k];
                if (cand < bestv) { bestv = cand; bestj = lane + 32*k + 1; }
            }
            unsigned key = __float_as_uint(bestv);
            key = (key & 0x80000000u) ? ~key : (key | 0x80000000u);
            unsigned mk = __reduce_min_sync(0xffffffffu, key);
            unsigned jc = (key == mk) ? (unsigned)bestj : 0xffffffffu;
            j0 = (int)__reduce_min_sync(0xffffffffu, jc);
            minVal = __uint_as_float((mk & 0x80000000u) ? (mk & 0x7fffffffu) : ~mk);
        }

        __syncwarp();
        // deferred dual update (p still pre-augmentation)
        #pragma unroll
        for (int k = 0; k < 4; k++) {
            if ((used >> k) & 1) {
                float d = minVal - minv[k];
                vreg[k] -= d;
                int row = p_sh[lane + 32*k + 1];
                u_sh[row] += d;     // distinct rows -> no collision
            }
        }
        if (lane == 0) u_sh[p_sh[0]] += minVal;
        __syncwarp();
        // augment along predecessor chain
        if (lane == 0) {
            int jj = sink;
            while (jj) { int w = way_sh[jj]; p_sh[jj] = p_sh[w]; jj = w; }
        }
        __syncwarp();
    }

    #pragma unroll
    for (int k = 0; k < 4; k++) {
        int j = lane + 32*k;
        g_rows[b*NN + j] = p_sh[j + 1] - 1;
    }
}

// ---------------- matched loss: one warp per (b,t) pair ----------------
__global__ void loss_kernel(const float* __restrict__ pred)
{
    __shared__ double s_part[7];
    if (threadIdx.x < 7) s_part[threadIdx.x] = 0.0;
    __syncthreads();

    int gw   = (blockIdx.x * blockDim.x + threadIdx.x) >> 5;
    int lane = threadIdx.x & 31;
    int b = gw >> 7;
    int r = g_rows[gw];                 // gw == b*128 + t
    size_t ip = (size_t)b * NN + r;
    size_t it = (size_t)gw;

    const float4* vp = (const float4*)(g_vp + ip * KP);
    const float4* vt = (const float4*)(g_vt + it * KP);

    float sla = 0.f;
    #pragma unroll
    for (int i = 0; i < 4; i++) {
        float4 a = vp[lane + 32*i];
        float4 c = vt[lane + 32*i];
        float dx = a.x - c.x, dy = a.y - c.y, dz = a.z - c.z, dw = a.w - c.w;
        sla = fmaf(dx, dx, sla); sla = fmaf(dy, dy, sla);
        sla = fmaf(dz, dz, sla); sla = fmaf(dw, dw, sla);
    }
    #pragma unroll
    for (int o = 16; o; o >>= 1) sla += __shfl_xor_sync(0xffffffffu, sla, o);

    if (lane < 18) {
        float diff = g_vp[ip*KP + 512 + lane] - g_vt[it*KP + 512 + lane];
        int s = (lane < 3) ? 1 : (lane < 6) ? 2 : (lane < 9) ? 3 : (lane < 12) ? 5 : 4;
        atomicAdd(&s_part[s], (double)(diff * diff));
    }
    if (lane == 0) {
        atomicAdd(&s_part[6], (double)sla);
        int cls = g_cls[it];
        float ce = g_logZ[ip] - pred[ip * DD + cls];
        atomicAdd(&s_part[0], (double)ce);
    }
    __syncthreads();
    if (threadIdx.x < 7) atomicAdd(&g_acc[threadIdx.x], s_part[threadIdx.x]);
}

// ---------------- finalize ----------------
__global__ void finalize_kernel(float* out, int out_size)
{
    if (threadIdx.x == 0) {
        double denom = 32768.0 + 1e-8;   // B*N + EPS
        double tot = 0.0;
        double st[7];
        for (int i = 0; i < 7; i++) { st[i] = g_acc[i]; tot += st[i]; }
        if (out_size >= 1) out[0] = (float)(tot / denom);
        for (int i = 0; i < 7; i++)
            if (out_size > i + 1) out[i + 1] = (float)(st[i] / denom);
    }
}

// ---------------- launch ----------------
extern "C" void kernel_launch(void* const* d_in, const int* in_sizes, int n_in,
                              void* d_out, int out_size)
{
    const float* pred   = (const float*)d_in[0];
    const float* target = (const float*)d_in[1];

    cudaFuncSetAttribute(cost_lsa_kernel, cudaFuncAttributeMaxDynamicSharedMemorySize, 81920);

    prep_kernel<<<(2*TOK)/8, 256>>>(pred, target);
    cost_lsa_kernel<<<BB, 256, 81920>>>(pred);
    loss_kernel<<<TOK/8, 256>>>(pred);
    finalize_kernel<<<1, 32>>>((float*)d_out, out_size);
}